// round 1
// baseline (speedup 1.0000x reference)
#include <cuda_runtime.h>

#define NN 50000
#define EE 500000
#define KK 3
#define DD 128
#define KD 384          // K*D
#define LOOP_ET 100     // 2R
#define NEG 0.2f
#define BN_EPS 1e-5f

// ---------------- scratch (static __device__ globals; no runtime alloc) ----------------
__device__ float g_x[(size_t)NN * KD];      // PCA output [N, K*D]
__device__ float g_out[(size_t)NN * KD];    // aggregated pre-BN
__device__ int   g_deg[NN];
__device__ int   g_off[NN + 1];
__device__ int   g_cur[NN];
__device__ int   g_edg[EE];                 // packed: src | (et<<17)
__device__ float g_sum[KD];
__device__ float g_sumsq[KD];
__device__ float g_a[KD];
__device__ float g_b[KD];

// ---------------- small float4 helpers ----------------
__device__ __forceinline__ float4 f4mul(float4 a, float4 b) {
    return make_float4(a.x * b.x, a.y * b.y, a.z * b.z, a.w * b.w);
}
__device__ __forceinline__ float dot4m(float4 a, float4 b) {
    return a.x * b.x + a.y * b.y + a.z * b.z + a.w * b.w;
}
__device__ __forceinline__ void f4fma(float4& acc, float4 m, float s) {
    acc.x += m.x * s; acc.y += m.y * s; acc.z += m.z * s; acc.w += m.w * s;
}

// ---------------- kernel 0: zero scratch counters ----------------
__global__ void k_zero() {
    int i = blockIdx.x * blockDim.x + threadIdx.x;
    if (i < NN) { g_deg[i] = 0; g_cur[i] = 0; }
    if (i < KD) { g_sum[i] = 0.f; g_sumsq[i] = 0.f; }
}

// ---------------- kernel 1: x = init_embed @ pca_w + pca_b ----------------
// [NN x 128] @ [128 x 384], BM=64 BN=128 BK=64, 256 threads, 48KB static smem
__global__ __launch_bounds__(256) void k_gemm(const float* __restrict__ A,
                                              const float* __restrict__ B,
                                              const float* __restrict__ bias) {
    __shared__ float As[64 * 64];
    __shared__ float Bs[64 * 128];
    int tid = threadIdx.x;
    int tx = tid & 31;      // 0..31  -> 4 cols each
    int ty = tid >> 5;      // 0..7   -> 8 rows each
    int row0 = blockIdx.x * 64;
    int col0 = blockIdx.y * 128;

    float acc[8][4];
#pragma unroll
    for (int i = 0; i < 8; i++) { acc[i][0] = acc[i][1] = acc[i][2] = acc[i][3] = 0.f; }

    for (int kk = 0; kk < 128; kk += 64) {
        // load A tile 64x64 (1024 float4, 4 per thread)
#pragma unroll
        for (int s = 0; s < 4; s++) {
            int idx = tid + s * 256;
            int r = idx >> 4, c4 = idx & 15;
            int gr = row0 + r;
            float4 v = make_float4(0.f, 0.f, 0.f, 0.f);
            if (gr < NN) v = *(const float4*)&A[(size_t)gr * DD + kk + c4 * 4];
            *(float4*)&As[r * 64 + c4 * 4] = v;
        }
        // load B tile 64x128 (2048 float4, 8 per thread)
#pragma unroll
        for (int s = 0; s < 8; s++) {
            int idx = tid + s * 256;
            int r = idx >> 5, c4 = idx & 31;
            *(float4*)&Bs[r * 128 + c4 * 4] =
                *(const float4*)&B[(size_t)(kk + r) * KD + col0 + c4 * 4];
        }
        __syncthreads();
#pragma unroll 16
        for (int k = 0; k < 64; k++) {
            float4 b = *(float4*)&Bs[k * 128 + tx * 4];
#pragma unroll
            for (int i = 0; i < 8; i++) {
                float a = As[(ty * 8 + i) * 64 + k];
                acc[i][0] += a * b.x; acc[i][1] += a * b.y;
                acc[i][2] += a * b.z; acc[i][3] += a * b.w;
            }
        }
        __syncthreads();
    }
    float4 bb = *(const float4*)&bias[col0 + tx * 4];
#pragma unroll
    for (int i = 0; i < 8; i++) {
        int gr = row0 + ty * 8 + i;
        if (gr < NN) {
            float4 v = make_float4(acc[i][0] + bb.x, acc[i][1] + bb.y,
                                   acc[i][2] + bb.z, acc[i][3] + bb.w);
            *(float4*)&g_x[(size_t)gr * KD + col0 + tx * 4] = v;
        }
    }
}

// ---------------- kernel 2: degree histogram over dst ----------------
__global__ void k_hist(const int* __restrict__ ei) {
    int e = blockIdx.x * blockDim.x + threadIdx.x;
    if (e < EE) atomicAdd(&g_deg[ei[EE + e]], 1);
}

// ---------------- kernel 3: exclusive scan (1 block, 1024 threads) ----------------
__global__ void k_scan() {
    __shared__ int wsum[32];
    __shared__ int carry;
    int t = threadIdx.x, lane = t & 31, wid = t >> 5;
    if (t == 0) { carry = 0; g_off[0] = 0; }
    __syncthreads();
    for (int base = 0; base < NN; base += 1024) {
        int v = (base + t < NN) ? g_deg[base + t] : 0;
        int x = v;
#pragma unroll
        for (int s = 1; s < 32; s <<= 1) {
            int y = __shfl_up_sync(0xffffffffu, x, s);
            if (lane >= s) x += y;
        }
        if (lane == 31) wsum[wid] = x;
        __syncthreads();
        if (wid == 0) {
            int y = wsum[lane];
#pragma unroll
            for (int s = 1; s < 32; s <<= 1) {
                int z = __shfl_up_sync(0xffffffffu, y, s);
                if (lane >= s) y += z;
            }
            wsum[lane] = y;
        }
        __syncthreads();
        int pre = (wid > 0) ? wsum[wid - 1] : 0;
        int incl = x + pre + carry;
        if (base + t < NN) g_off[base + t + 1] = incl;
        __syncthreads();
        if (t == 1023) carry = incl;
        __syncthreads();
    }
}

// ---------------- kernel 4: scatter edges into CSR ----------------
__global__ void k_scatter(const int* __restrict__ ei, const int* __restrict__ et) {
    int e = blockIdx.x * blockDim.x + threadIdx.x;
    if (e < EE) {
        int dst = ei[EE + e];
        int pos = g_off[dst] + atomicAdd(&g_cur[dst], 1);
        g_edg[pos] = ei[e] | (et[e] << 17);
    }
}

// ---------------- kernel 5: per-node message + attention + aggregate ----------------
// one warp per destination node; lane owns 4 contiguous dims of D=128 per factor
__global__ __launch_bounds__(256) void k_agg(const float* __restrict__ init_rel,
                                             const float* __restrict__ loop_rel,
                                             const float* __restrict__ rel_weight) {
    int warp = (blockIdx.x * 256 + threadIdx.x) >> 5;
    int lane = threadIdx.x & 31;
    if (warp >= NN) return;
    int node = warp;

    const float4* xrow = (const float4*)(g_x + (size_t)node * KD);
    float4 xi0 = __ldcg(xrow + lane);
    float4 xi1 = __ldcg(xrow + 32 + lane);
    float4 xi2 = __ldcg(xrow + 64 + lane);

    float4 acc0 = make_float4(0, 0, 0, 0);
    float4 acc1 = make_float4(0, 0, 0, 0);
    float4 acc2 = make_float4(0, 0, 0, 0);
    float den0 = 0.f, den1 = 0.f, den2 = 0.f;

    int beg = g_off[node], end = g_off[node + 1];
    for (int e = beg; e <= end; e++) {
        int et;
        float4 xj0, xj1, xj2;
        if (e < end) {
            int p = g_edg[e];
            int src = p & 0x1FFFF;
            et = p >> 17;
            const float4* xs = (const float4*)(g_x + (size_t)src * KD);
            xj0 = __ldcg(xs + lane);
            xj1 = __ldcg(xs + 32 + lane);
            xj2 = __ldcg(xs + 64 + lane);
        } else {                 // self loop
            et = LOOP_ET;
            xj0 = xi0; xj1 = xi1; xj2 = xi2;
        }
        const float4* w4 = (const float4*)(rel_weight + (size_t)et * (KK * DD));
        const float4* r4 = (const float4*)((et < LOOP_ET) ? (init_rel + (size_t)et * DD)
                                                          : loop_rel);
        float4 r  = __ldg(r4 + lane);
        float4 w0 = __ldg(w4 + lane);
        float4 w1 = __ldg(w4 + 32 + lane);
        float4 w2 = __ldg(w4 + 64 + lane);

        float4 jw0 = f4mul(xj0, w0);
        float4 jw1 = f4mul(xj1, w1);
        float4 jw2 = f4mul(xj2, w2);

        float p0 = dot4m(f4mul(xi0, w0), jw0);
        float p1 = dot4m(f4mul(xi1, w1), jw1);
        float p2 = dot4m(f4mul(xi2, w2), jw2);
#pragma unroll
        for (int s = 16; s; s >>= 1) {
            p0 += __shfl_xor_sync(0xffffffffu, p0, s);
            p1 += __shfl_xor_sync(0xffffffffu, p1, s);
            p2 += __shfl_xor_sync(0xffffffffu, p2, s);
        }
        float a0 = p0 > 0.f ? p0 : NEG * p0;
        float a1 = p1 > 0.f ? p1 : NEG * p1;
        float a2 = p2 > 0.f ? p2 : NEG * p2;
        float e0 = __expf(a0), e1 = __expf(a1), e2 = __expf(a2);
        den0 += e0; den1 += e1; den2 += e2;

        float4 rp = make_float4(r.x + 1.f, r.y + 1.f, r.z + 1.f, r.w + 1.f);
        f4fma(acc0, f4mul(jw0, rp), e0);
        f4fma(acc1, f4mul(jw1, rp), e1);
        f4fma(acc2, f4mul(jw2, rp), e2);
    }

    float i0 = 1.f / (den0 + 1e-16f);
    float i1 = 1.f / (den1 + 1e-16f);
    float i2 = 1.f / (den2 + 1e-16f);
    float4* orow = (float4*)(g_out + (size_t)node * KD);
    orow[lane]      = make_float4(acc0.x * i0, acc0.y * i0, acc0.z * i0, acc0.w * i0);
    orow[32 + lane] = make_float4(acc1.x * i1, acc1.y * i1, acc1.z * i1, acc1.w * i1);
    orow[64 + lane] = make_float4(acc2.x * i2, acc2.y * i2, acc2.z * i2, acc2.w * i2);
}

// ---------------- kernel 6: BN column stats (partial sums + atomics) ----------------
__global__ void k_bnstats() {
    int col = threadIdx.x;   // blockDim = 384
    float s = 0.f, s2 = 0.f;
    for (int row = blockIdx.x; row < NN; row += gridDim.x) {
        float v = g_out[(size_t)row * KD + col];
        s += v; s2 += v * v;
    }
    atomicAdd(&g_sum[col], s);
    atomicAdd(&g_sumsq[col], s2);
}

// ---------------- kernel 7: finalize BN affine coefficients ----------------
__global__ void k_bnfinal(const float* __restrict__ gamma, const float* __restrict__ beta) {
    int c = threadIdx.x;
    if (c < KD) {
        float mu = g_sum[c] / (float)NN;
        float var = g_sumsq[c] / (float)NN - mu * mu;
        float a = gamma[c] * rsqrtf(var + BN_EPS);
        g_a[c] = a;
        g_b[c] = beta[c] - mu * a;
    }
}

// ---------------- kernel 8: normalize + tanh -> d_out ----------------
__global__ void k_apply(float* __restrict__ out) {
    int i = blockIdx.x * blockDim.x + threadIdx.x;   // float4 index
    if (i < NN * (KD / 4)) {
        int c4 = (i % (KD / 4)) * 4;
        float4 v = *(const float4*)&g_out[(size_t)i * 4];
        float4 y;
        y.x = tanhf(v.x * g_a[c4 + 0] + g_b[c4 + 0]);
        y.y = tanhf(v.y * g_a[c4 + 1] + g_b[c4 + 1]);
        y.z = tanhf(v.z * g_a[c4 + 2] + g_b[c4 + 2]);
        y.w = tanhf(v.w * g_a[c4 + 3] + g_b[c4 + 3]);
        ((float4*)out)[i] = y;
    }
}

// ---------------- launch ----------------
extern "C" void kernel_launch(void* const* d_in, const int* in_sizes, int n_in,
                              void* d_out, int out_size) {
    const float* init_embed = (const float*)d_in[0];
    const float* init_rel   = (const float*)d_in[1];
    const float* pca_w      = (const float*)d_in[2];
    const float* pca_b      = (const float*)d_in[3];
    const float* loop_rel   = (const float*)d_in[4];
    const float* rel_weight = (const float*)d_in[5];
    const float* bn_gamma   = (const float*)d_in[6];
    const float* bn_beta    = (const float*)d_in[7];
    const int*   edge_index = (const int*)d_in[8];
    const int*   edge_type  = (const int*)d_in[9];
    float* out = (float*)d_out;

    k_zero<<<(NN + 255) / 256, 256>>>();

    dim3 gg((NN + 63) / 64, KD / 128);
    k_gemm<<<gg, 256>>>(init_embed, pca_w, pca_b);

    k_hist<<<(EE + 255) / 256, 256>>>(edge_index);
    k_scan<<<1, 1024>>>();
    k_scatter<<<(EE + 255) / 256, 256>>>(edge_index, edge_type);

    k_agg<<<(NN * 32 + 255) / 256, 256>>>(init_rel, loop_rel, rel_weight);

    k_bnstats<<<512, 384>>>();
    k_bnfinal<<<1, 384>>>(bn_gamma, bn_beta);
    k_apply<<<(NN * (KD / 4) + 255) / 256, 256>>>(out);
}

// round 4
// speedup vs baseline: 1.1406x; 1.1406x over previous
#include <cuda_runtime.h>
#include <cuda_bf16.h>
#include <cstdint>

#define NN 50000
#define EE 500000
#define KK 3
#define DD 128
#define KD 384          // K*D
#define LOOP_ET 100     // 2R
#define NEG 0.2f
#define BN_EPS 1e-5f
#define NBLK 196        // ceil(NN/256)

// ---------------- scratch (static __device__ globals; no runtime alloc) ----------------
__device__ float g_x[(size_t)NN * KD];      // PCA output [N, K*D]
__device__ float g_out[(size_t)NN * KD];    // aggregated pre-BN
__device__ int   g_deg[NN];
__device__ int   g_off[NN + 1];
__device__ int   g_cur[NN];
__device__ int   g_edg[EE];                 // packed: src | (et<<17)
__device__ int   g_bsum[NBLK];
__device__ int   g_bpre[NBLK];
__device__ float g_sum[KD];
__device__ float g_sumsq[KD];
__device__ float g_a[KD];
__device__ float g_b[KD];

// ---------------- small float4 helpers ----------------
__device__ __forceinline__ float4 f4mul(float4 a, float4 b) {
    return make_float4(a.x * b.x, a.y * b.y, a.z * b.z, a.w * b.w);
}
__device__ __forceinline__ float dot4m(float4 a, float4 b) {
    return a.x * b.x + a.y * b.y + a.z * b.z + a.w * b.w;
}
__device__ __forceinline__ void f4fma(float4& acc, float4 m, float s) {
    acc.x += m.x * s; acc.y += m.y * s; acc.z += m.z * s; acc.w += m.w * s;
}

// ---------------- bf16 split helpers ----------------
__device__ __forceinline__ void split2(float x, float y, uint32_t& h, uint32_t& l) {
    __nv_bfloat16 hx = __float2bfloat16_rn(x);
    __nv_bfloat16 hy = __float2bfloat16_rn(y);
    float rx = x - __bfloat162float(hx);
    float ry = y - __bfloat162float(hy);
    __nv_bfloat16 lx = __float2bfloat16_rn(rx);
    __nv_bfloat16 ly = __float2bfloat16_rn(ry);
    uint16_t uhx = *(uint16_t*)&hx, uhy = *(uint16_t*)&hy;
    uint16_t ulx = *(uint16_t*)&lx, uly = *(uint16_t*)&ly;
    h = (uint32_t)uhx | ((uint32_t)uhy << 16);
    l = (uint32_t)ulx | ((uint32_t)uly << 16);
}

__device__ __forceinline__ void mma16816(float* c, const uint32_t* a,
                                         uint32_t b0, uint32_t b1) {
    asm volatile(
        "mma.sync.aligned.m16n8k16.row.col.f32.bf16.bf16.f32 "
        "{%0,%1,%2,%3}, {%4,%5,%6,%7}, {%8,%9}, {%0,%1,%2,%3};"
        : "+f"(c[0]), "+f"(c[1]), "+f"(c[2]), "+f"(c[3])
        : "r"(a[0]), "r"(a[1]), "r"(a[2]), "r"(a[3]), "r"(b0), "r"(b1));
}

// ---------------- kernel 0: zero scratch counters ----------------
__global__ void k_zero() {
    int i = blockIdx.x * blockDim.x + threadIdx.x;
    if (i < NN) { g_deg[i] = 0; g_cur[i] = 0; }
    if (i < KD) { g_sum[i] = 0.f; g_sumsq[i] = 0.f; }
}

// ---------------- kernel 1: x = init_embed @ pca_w + pca_b  (bf16 3xMMA) ----------------
// BM=128, BN=128, BK=32, 256 threads (8 warps: 4m x 2n), warp tile 32x64.
// smem: k-pair-packed u32, A stride 18 (16 pairs + 2 pad), B stride 19.
__global__ __launch_bounds__(256) void k_gemm(const float* __restrict__ A,
                                              const float* __restrict__ B,
                                              const float* __restrict__ bias) {
    __shared__ uint32_t As_h[128 * 18], As_l[128 * 18];
    __shared__ uint32_t Bs_h[128 * 19], Bs_l[128 * 19];
    int tid = threadIdx.x;
    int warp = tid >> 5, lane = tid & 31;
    int g = lane >> 2, t = lane & 3;
    int wm = warp >> 1, wn = warp & 1;
    int row0 = blockIdx.x * 128;
    int col0 = blockIdx.y * 128;

    float c[2][8][4];
#pragma unroll
    for (int mi = 0; mi < 2; mi++)
#pragma unroll
        for (int ni = 0; ni < 8; ni++)
#pragma unroll
            for (int j = 0; j < 4; j++) c[mi][ni][j] = 0.f;

    int bn = tid & 127;         // n index for B staging
    int pb0 = tid >> 7;         // 0 or 1

    for (int kb = 0; kb < 4; kb++) {
        // stage A: 128 rows x 32 k (fp32 -> hi/lo bf16 pairs)
#pragma unroll
        for (int s = 0; s < 4; s++) {
            int idx = tid + s * 256;
            int r = idx >> 3, c4 = idx & 7;
            int gr = row0 + r;
            float4 v = make_float4(0.f, 0.f, 0.f, 0.f);
            if (gr < NN) v = *(const float4*)&A[(size_t)gr * DD + kb * 32 + c4 * 4];
            uint32_t h0, l0, h1, l1;
            split2(v.x, v.y, h0, l0);
            split2(v.z, v.w, h1, l1);
            As_h[r * 18 + c4 * 2] = h0; As_h[r * 18 + c4 * 2 + 1] = h1;
            As_l[r * 18 + c4 * 2] = l0; As_l[r * 18 + c4 * 2 + 1] = l1;
        }
        // stage B: 32 k x 128 n, transposed to [n][kpair]
#pragma unroll
        for (int s = 0; s < 8; s++) {
            int p = pb0 + s * 2;                 // k-pair 0..15
            int kg = kb * 32 + 2 * p;
            float b0f = B[(size_t)kg * KD + col0 + bn];
            float b1f = B[(size_t)(kg + 1) * KD + col0 + bn];
            uint32_t h, l;
            split2(b0f, b1f, h, l);
            Bs_h[bn * 19 + p] = h;
            Bs_l[bn * 19 + p] = l;
        }
        __syncthreads();

#pragma unroll
        for (int ki = 0; ki < 2; ki++) {
            int pb = ki * 8;
            uint32_t ah[2][4], al[2][4];
#pragma unroll
            for (int mi = 0; mi < 2; mi++) {
                int r0 = (wm * 32 + mi * 16 + g) * 18;
                int r1 = r0 + 8 * 18;
                ah[mi][0] = As_h[r0 + pb + t];     ah[mi][1] = As_h[r1 + pb + t];
                ah[mi][2] = As_h[r0 + pb + 4 + t]; ah[mi][3] = As_h[r1 + pb + 4 + t];
                al[mi][0] = As_l[r0 + pb + t];     al[mi][1] = As_l[r1 + pb + t];
                al[mi][2] = As_l[r0 + pb + 4 + t]; al[mi][3] = As_l[r1 + pb + 4 + t];
            }
#pragma unroll
            for (int ni = 0; ni < 8; ni++) {
                int n = (wn * 64 + ni * 8 + g) * 19;
                uint32_t bh0 = Bs_h[n + pb + t], bh1 = Bs_h[n + pb + 4 + t];
                uint32_t bl0 = Bs_l[n + pb + t], bl1 = Bs_l[n + pb + 4 + t];
#pragma unroll
                for (int mi = 0; mi < 2; mi++) {
                    mma16816(c[mi][ni], ah[mi], bh0, bh1);   // hi*hi
                    mma16816(c[mi][ni], ah[mi], bl0, bl1);   // hi*lo
                    mma16816(c[mi][ni], al[mi], bh0, bh1);   // lo*hi
                }
            }
        }
        __syncthreads();
    }

    // store + bias
#pragma unroll
    for (int mi = 0; mi < 2; mi++) {
        int row = row0 + wm * 32 + mi * 16 + g;
#pragma unroll
        for (int ni = 0; ni < 8; ni++) {
            int col = col0 + wn * 64 + ni * 8 + 2 * t;
            float bx = __ldg(&bias[col]), by = __ldg(&bias[col + 1]);
            if (row < NN) {
                float2 v0 = make_float2(c[mi][ni][0] + bx, c[mi][ni][1] + by);
                *(float2*)&g_x[(size_t)row * KD + col] = v0;
            }
            if (row + 8 < NN) {
                float2 v1 = make_float2(c[mi][ni][2] + bx, c[mi][ni][3] + by);
                *(float2*)&g_x[(size_t)(row + 8) * KD + col] = v1;
            }
        }
    }
}

// ---------------- kernel 2: degree histogram over dst ----------------
__global__ void k_hist(const int* __restrict__ ei) {
    int e = blockIdx.x * blockDim.x + threadIdx.x;
    if (e < EE) atomicAdd(&g_deg[ei[EE + e]], 1);
}

// ---------------- scan: 3-kernel parallel version ----------------
__device__ __forceinline__ int block_scan_256(int v, int* wsum, int nw) {
    int lane = threadIdx.x & 31, wid = threadIdx.x >> 5;
    int x = v;
#pragma unroll
    for (int s = 1; s < 32; s <<= 1) {
        int y = __shfl_up_sync(0xffffffffu, x, s);
        if (lane >= s) x += y;
    }
    if (lane == 31) wsum[wid] = x;
    __syncthreads();
    if (wid == 0) {
        int y = (lane < nw) ? wsum[lane] : 0;
#pragma unroll
        for (int s = 1; s < 8; s <<= 1) {
            int z = __shfl_up_sync(0xffffffffu, y, s);
            if (lane >= s) y += z;
        }
        if (lane < nw) wsum[lane] = y;
    }
    __syncthreads();
    return x + (wid > 0 ? wsum[wid - 1] : 0);   // inclusive
}

__global__ void k_scanA() {   // per-block sums
    __shared__ int wsum[8];
    int i = blockIdx.x * 256 + threadIdx.x;
    int v = (i < NN) ? g_deg[i] : 0;
    int incl = block_scan_256(v, wsum, 8);
    if (threadIdx.x == 255) g_bsum[blockIdx.x] = incl;
}
__global__ void k_scanB() {   // scan the 196 block sums (1 block, 224 thr)
    __shared__ int wsum[8];
    int i = threadIdx.x;
    int v = (i < NBLK) ? g_bsum[i] : 0;
    int incl = block_scan_256(v, wsum, 7);
    if (i < NBLK) g_bpre[i] = incl - v;   // exclusive
}
__global__ void k_scanC() {   // final offsets
    __shared__ int wsum[8];
    int i = blockIdx.x * 256 + threadIdx.x;
    int v = (i < NN) ? g_deg[i] : 0;
    int incl = block_scan_256(v, wsum, 8);
    if (i < NN) g_off[i + 1] = incl + g_bpre[blockIdx.x];
    if (i == 0) g_off[0] = 0;
}

// ---------------- kernel 4: scatter edges into CSR ----------------
__global__ void k_scatter(const int* __restrict__ ei, const int* __restrict__ et) {
    int e = blockIdx.x * blockDim.x + threadIdx.x;
    if (e < EE) {
        int dst = ei[EE + e];
        int pos = g_off[dst] + atomicAdd(&g_cur[dst], 1);
        g_edg[pos] = ei[e] | (et[e] << 17);
    }
}

// ---------------- kernel 5: per-node message + attention + aggregate ----------------
__global__ __launch_bounds__(256) void k_agg(const float* __restrict__ init_rel,
                                             const float* __restrict__ loop_rel,
                                             const float* __restrict__ rel_weight) {
    int warp = (blockIdx.x * 256 + threadIdx.x) >> 5;
    int lane = threadIdx.x & 31;
    if (warp >= NN) return;
    int node = warp;

    const float4* xrow = (const float4*)(g_x + (size_t)node * KD);
    float4 xi0 = __ldcg(xrow + lane);
    float4 xi1 = __ldcg(xrow + 32 + lane);
    float4 xi2 = __ldcg(xrow + 64 + lane);

    float4 acc0 = make_float4(0, 0, 0, 0);
    float4 acc1 = make_float4(0, 0, 0, 0);
    float4 acc2 = make_float4(0, 0, 0, 0);
    float den0 = 0.f, den1 = 0.f, den2 = 0.f;

    int beg = g_off[node], end = g_off[node + 1];
    for (int e = beg; e <= end; e++) {
        int et;
        float4 xj0, xj1, xj2;
        if (e < end) {
            int p = g_edg[e];
            int src = p & 0x1FFFF;
            et = p >> 17;
            const float4* xs = (const float4*)(g_x + (size_t)src * KD);
            xj0 = __ldcg(xs + lane);
            xj1 = __ldcg(xs + 32 + lane);
            xj2 = __ldcg(xs + 64 + lane);
        } else {                 // self loop
            et = LOOP_ET;
            xj0 = xi0; xj1 = xi1; xj2 = xi2;
        }
        const float4* w4 = (const float4*)(rel_weight + (size_t)et * (KK * DD));
        const float4* r4 = (const float4*)((et < LOOP_ET) ? (init_rel + (size_t)et * DD)
                                                          : loop_rel);
        float4 r  = __ldg(r4 + lane);
        float4 w0 = __ldg(w4 + lane);
        float4 w1 = __ldg(w4 + 32 + lane);
        float4 w2 = __ldg(w4 + 64 + lane);

        float4 jw0 = f4mul(xj0, w0);
        float4 jw1 = f4mul(xj1, w1);
        float4 jw2 = f4mul(xj2, w2);

        float p0 = dot4m(f4mul(xi0, w0), jw0);
        float p1 = dot4m(f4mul(xi1, w1), jw1);
        float p2 = dot4m(f4mul(xi2, w2), jw2);
#pragma unroll
        for (int s = 16; s; s >>= 1) {
            p0 += __shfl_xor_sync(0xffffffffu, p0, s);
            p1 += __shfl_xor_sync(0xffffffffu, p1, s);
            p2 += __shfl_xor_sync(0xffffffffu, p2, s);
        }
        float a0 = p0 > 0.f ? p0 : NEG * p0;
        float a1 = p1 > 0.f ? p1 : NEG * p1;
        float a2 = p2 > 0.f ? p2 : NEG * p2;
        float e0 = __expf(a0), e1 = __expf(a1), e2 = __expf(a2);
        den0 += e0; den1 += e1; den2 += e2;

        float4 rp = make_float4(r.x + 1.f, r.y + 1.f, r.z + 1.f, r.w + 1.f);
        f4fma(acc0, f4mul(jw0, rp), e0);
        f4fma(acc1, f4mul(jw1, rp), e1);
        f4fma(acc2, f4mul(jw2, rp), e2);
    }

    float i0 = 1.f / (den0 + 1e-16f);
    float i1 = 1.f / (den1 + 1e-16f);
    float i2 = 1.f / (den2 + 1e-16f);
    float4* orow = (float4*)(g_out + (size_t)node * KD);
    orow[lane]      = make_float4(acc0.x * i0, acc0.y * i0, acc0.z * i0, acc0.w * i0);
    orow[32 + lane] = make_float4(acc1.x * i1, acc1.y * i1, acc1.z * i1, acc1.w * i1);
    orow[64 + lane] = make_float4(acc2.x * i2, acc2.y * i2, acc2.z * i2, acc2.w * i2);
}

// ---------------- kernel 6: BN column stats ----------------
__global__ void k_bnstats() {
    int col = threadIdx.x;   // blockDim = 384
    float s = 0.f, s2 = 0.f;
    for (int row = blockIdx.x; row < NN; row += gridDim.x) {
        float v = g_out[(size_t)row * KD + col];
        s += v; s2 += v * v;
    }
    atomicAdd(&g_sum[col], s);
    atomicAdd(&g_sumsq[col], s2);
}

// ---------------- kernel 7: finalize BN coefficients ----------------
__global__ void k_bnfinal(const float* __restrict__ gamma, const float* __restrict__ beta) {
    int c = threadIdx.x;
    if (c < KD) {
        float mu = g_sum[c] / (float)NN;
        float var = g_sumsq[c] / (float)NN - mu * mu;
        float a = gamma[c] * rsqrtf(var + BN_EPS);
        g_a[c] = a;
        g_b[c] = beta[c] - mu * a;
    }
}

// ---------------- kernel 8: normalize + tanh -> d_out ----------------
__global__ void k_apply(float* __restrict__ out) {
    int i = blockIdx.x * blockDim.x + threadIdx.x;   // float4 index
    if (i < NN * (KD / 4)) {
        int c4 = (i % (KD / 4)) * 4;
        float4 v = *(const float4*)&g_out[(size_t)i * 4];
        float4 y;
        y.x = tanhf(v.x * g_a[c4 + 0] + g_b[c4 + 0]);
        y.y = tanhf(v.y * g_a[c4 + 1] + g_b[c4 + 1]);
        y.z = tanhf(v.z * g_a[c4 + 2] + g_b[c4 + 2]);
        y.w = tanhf(v.w * g_a[c4 + 3] + g_b[c4 + 3]);
        ((float4*)out)[i] = y;
    }
}

// ---------------- launch ----------------
extern "C" void kernel_launch(void* const* d_in, const int* in_sizes, int n_in,
                              void* d_out, int out_size) {
    const float* init_embed = (const float*)d_in[0];
    const float* init_rel   = (const float*)d_in[1];
    const float* pca_w      = (const float*)d_in[2];
    const float* pca_b      = (const float*)d_in[3];
    const float* loop_rel   = (const float*)d_in[4];
    const float* rel_weight = (const float*)d_in[5];
    const float* bn_gamma   = (const float*)d_in[6];
    const float* bn_beta    = (const float*)d_in[7];
    const int*   edge_index = (const int*)d_in[8];
    const int*   edge_type  = (const int*)d_in[9];
    float* out = (float*)d_out;

    k_zero<<<(NN + 255) / 256, 256>>>();

    dim3 gg((NN + 127) / 128, KD / 128);
    k_gemm<<<gg, 256>>>(init_embed, pca_w, pca_b);

    k_hist<<<(EE + 255) / 256, 256>>>(edge_index);
    k_scanA<<<NBLK, 256>>>();
    k_scanB<<<1, 224>>>();
    k_scanC<<<NBLK, 256>>>();
    k_scatter<<<(EE + 255) / 256, 256>>>(edge_index, edge_type);

    k_agg<<<(NN * 32 + 255) / 256, 256>>>(init_rel, loop_rel, rel_weight);

    k_bnstats<<<512, 384>>>();
    k_bnfinal<<<1, 384>>>(bn_gamma, bn_beta);
    k_apply<<<(NN * (KD / 4) + 255) / 256, 256>>>(out);
}

// round 5
// speedup vs baseline: 1.1797x; 1.0343x over previous
#include <cuda_runtime.h>
#include <cuda_bf16.h>
#include <cstdint>

#define NN 50000
#define EE 500000
#define KK 3
#define DD 128
#define KD 384          // K*D
#define LOOP_ET 100     // 2R
#define NEG 0.2f
#define BN_EPS 1e-5f
#define NBLK 196        // ceil(NN/256)

// ---------------- scratch (static __device__ globals; no runtime alloc) ----------------
__device__ float g_x[(size_t)NN * KD];      // PCA output [N, K*D]
__device__ float g_out[(size_t)NN * KD];    // aggregated pre-BN
__device__ int   g_deg[NN];
__device__ int   g_off[NN + 1];
__device__ int   g_cur[NN];
__device__ int   g_edg[EE];                 // packed: src | (et<<17)
__device__ int   g_bsum[NBLK];
__device__ float g_sum[KD];
__device__ float g_sumsq[KD];
__device__ float g_a[KD];
__device__ float g_b[KD];

// ---------------- small float4 helpers ----------------
__device__ __forceinline__ float4 f4mul(float4 a, float4 b) {
    return make_float4(a.x * b.x, a.y * b.y, a.z * b.z, a.w * b.w);
}
__device__ __forceinline__ float dot4m(float4 a, float4 b) {
    return a.x * b.x + a.y * b.y + a.z * b.z + a.w * b.w;
}
__device__ __forceinline__ void f4fma(float4& acc, float4 m, float s) {
    acc.x += m.x * s; acc.y += m.y * s; acc.z += m.z * s; acc.w += m.w * s;
}
__device__ __forceinline__ float fast_tanh(float x) {
    float y;
    asm("tanh.approx.f32 %0, %1;" : "=f"(y) : "f"(x));
    return y;
}

// ---------------- bf16 split helpers ----------------
__device__ __forceinline__ void split2(float x, float y, uint32_t& h, uint32_t& l) {
    __nv_bfloat16 hx = __float2bfloat16_rn(x);
    __nv_bfloat16 hy = __float2bfloat16_rn(y);
    float rx = x - __bfloat162float(hx);
    float ry = y - __bfloat162float(hy);
    __nv_bfloat16 lx = __float2bfloat16_rn(rx);
    __nv_bfloat16 ly = __float2bfloat16_rn(ry);
    uint16_t uhx = *(uint16_t*)&hx, uhy = *(uint16_t*)&hy;
    uint16_t ulx = *(uint16_t*)&lx, uly = *(uint16_t*)&ly;
    h = (uint32_t)uhx | ((uint32_t)uhy << 16);
    l = (uint32_t)ulx | ((uint32_t)uly << 16);
}

__device__ __forceinline__ void mma16816(float* c, const uint32_t* a,
                                         uint32_t b0, uint32_t b1) {
    asm volatile(
        "mma.sync.aligned.m16n8k16.row.col.f32.bf16.bf16.f32 "
        "{%0,%1,%2,%3}, {%4,%5,%6,%7}, {%8,%9}, {%0,%1,%2,%3};"
        : "+f"(c[0]), "+f"(c[1]), "+f"(c[2]), "+f"(c[3])
        : "r"(a[0]), "r"(a[1]), "r"(a[2]), "r"(a[3]), "r"(b0), "r"(b1));
}

// ---------------- kernel: zero scratch counters ----------------
__global__ void k_zero() {
    int i = blockIdx.x * blockDim.x + threadIdx.x;
    if (i < NN) { g_deg[i] = 0; g_cur[i] = 0; }
    if (i < KD) { g_sum[i] = 0.f; g_sumsq[i] = 0.f; }
}

// ---------------- kernel: x = init_embed @ pca_w + pca_b  (bf16 3xMMA) ----------------
__global__ __launch_bounds__(256) void k_gemm(const float* __restrict__ A,
                                              const float* __restrict__ B,
                                              const float* __restrict__ bias) {
    __shared__ uint32_t As_h[128 * 18], As_l[128 * 18];
    __shared__ uint32_t Bs_h[128 * 19], Bs_l[128 * 19];
    int tid = threadIdx.x;
    int warp = tid >> 5, lane = tid & 31;
    int g = lane >> 2, t = lane & 3;
    int wm = warp >> 1, wn = warp & 1;
    int row0 = blockIdx.x * 128;
    int col0 = blockIdx.y * 128;

    float c[2][8][4];
#pragma unroll
    for (int mi = 0; mi < 2; mi++)
#pragma unroll
        for (int ni = 0; ni < 8; ni++)
#pragma unroll
            for (int j = 0; j < 4; j++) c[mi][ni][j] = 0.f;

    int bn = tid & 127;
    int pb0 = tid >> 7;

    for (int kb = 0; kb < 4; kb++) {
#pragma unroll
        for (int s = 0; s < 4; s++) {
            int idx = tid + s * 256;
            int r = idx >> 3, c4 = idx & 7;
            int gr = row0 + r;
            float4 v = make_float4(0.f, 0.f, 0.f, 0.f);
            if (gr < NN) v = *(const float4*)&A[(size_t)gr * DD + kb * 32 + c4 * 4];
            uint32_t h0, l0, h1, l1;
            split2(v.x, v.y, h0, l0);
            split2(v.z, v.w, h1, l1);
            As_h[r * 18 + c4 * 2] = h0; As_h[r * 18 + c4 * 2 + 1] = h1;
            As_l[r * 18 + c4 * 2] = l0; As_l[r * 18 + c4 * 2 + 1] = l1;
        }
#pragma unroll
        for (int s = 0; s < 8; s++) {
            int p = pb0 + s * 2;
            int kg = kb * 32 + 2 * p;
            float b0f = B[(size_t)kg * KD + col0 + bn];
            float b1f = B[(size_t)(kg + 1) * KD + col0 + bn];
            uint32_t h, l;
            split2(b0f, b1f, h, l);
            Bs_h[bn * 19 + p] = h;
            Bs_l[bn * 19 + p] = l;
        }
        __syncthreads();

#pragma unroll
        for (int ki = 0; ki < 2; ki++) {
            int pb = ki * 8;
            uint32_t ah[2][4], al[2][4];
#pragma unroll
            for (int mi = 0; mi < 2; mi++) {
                int r0 = (wm * 32 + mi * 16 + g) * 18;
                int r1 = r0 + 8 * 18;
                ah[mi][0] = As_h[r0 + pb + t];     ah[mi][1] = As_h[r1 + pb + t];
                ah[mi][2] = As_h[r0 + pb + 4 + t]; ah[mi][3] = As_h[r1 + pb + 4 + t];
                al[mi][0] = As_l[r0 + pb + t];     al[mi][1] = As_l[r1 + pb + t];
                al[mi][2] = As_l[r0 + pb + 4 + t]; al[mi][3] = As_l[r1 + pb + 4 + t];
            }
#pragma unroll
            for (int ni = 0; ni < 8; ni++) {
                int n = (wn * 64 + ni * 8 + g) * 19;
                uint32_t bh0 = Bs_h[n + pb + t], bh1 = Bs_h[n + pb + 4 + t];
                uint32_t bl0 = Bs_l[n + pb + t], bl1 = Bs_l[n + pb + 4 + t];
#pragma unroll
                for (int mi = 0; mi < 2; mi++) {
                    mma16816(c[mi][ni], ah[mi], bh0, bh1);   // hi*hi
                    mma16816(c[mi][ni], ah[mi], bl0, bl1);   // hi*lo
                    mma16816(c[mi][ni], al[mi], bh0, bh1);   // lo*hi
                }
            }
        }
        __syncthreads();
    }

#pragma unroll
    for (int mi = 0; mi < 2; mi++) {
        int row = row0 + wm * 32 + mi * 16 + g;
#pragma unroll
        for (int ni = 0; ni < 8; ni++) {
            int col = col0 + wn * 64 + ni * 8 + 2 * t;
            float bx = __ldg(&bias[col]), by = __ldg(&bias[col + 1]);
            if (row < NN) {
                float2 v0 = make_float2(c[mi][ni][0] + bx, c[mi][ni][1] + by);
                *(float2*)&g_x[(size_t)row * KD + col] = v0;
            }
            if (row + 8 < NN) {
                float2 v1 = make_float2(c[mi][ni][2] + bx, c[mi][ni][3] + by);
                *(float2*)&g_x[(size_t)(row + 8) * KD + col] = v1;
            }
        }
    }
}

// ---------------- kernel: degree histogram over dst ----------------
__global__ void k_hist(const int* __restrict__ ei) {
    int e = blockIdx.x * blockDim.x + threadIdx.x;
    if (e < EE) atomicAdd(&g_deg[ei[EE + e]], 1);
}

// ---------------- scan ----------------
__device__ __forceinline__ int block_scan_256(int v, int* wsum) {
    int lane = threadIdx.x & 31, wid = threadIdx.x >> 5;
    int x = v;
#pragma unroll
    for (int s = 1; s < 32; s <<= 1) {
        int y = __shfl_up_sync(0xffffffffu, x, s);
        if (lane >= s) x += y;
    }
    if (lane == 31) wsum[wid] = x;
    __syncthreads();
    if (wid == 0) {
        int y = (lane < 8) ? wsum[lane] : 0;
#pragma unroll
        for (int s = 1; s < 8; s <<= 1) {
            int z = __shfl_up_sync(0xffffffffu, y, s);
            if (lane >= s) y += z;
        }
        if (lane < 8) wsum[lane] = y;
    }
    __syncthreads();
    return x + (wid > 0 ? wsum[wid - 1] : 0);   // inclusive
}

__global__ void k_scanA() {   // per-block sums
    __shared__ int wsum[8];
    int i = blockIdx.x * 256 + threadIdx.x;
    int v = (i < NN) ? g_deg[i] : 0;
    int incl = block_scan_256(v, wsum);
    if (threadIdx.x == 255) g_bsum[blockIdx.x] = incl;
}

// final offsets; each block computes its own prefix over g_bsum (196 ints)
__global__ void k_scanC() {
    __shared__ int wsum[8];
    __shared__ int s_pre;
    int t = threadIdx.x, lane = t & 31, wid = t >> 5;

    int acc = 0;
    for (int i = t; i < blockIdx.x; i += 256) acc += g_bsum[i];
#pragma unroll
    for (int s = 16; s; s >>= 1) acc += __shfl_xor_sync(0xffffffffu, acc, s);
    if (lane == 0) wsum[wid] = acc;
    __syncthreads();
    if (t == 0) {
        int tot = 0;
#pragma unroll
        for (int w = 0; w < 8; w++) tot += wsum[w];
        s_pre = tot;
    }
    __syncthreads();
    int pre = s_pre;
    __syncthreads();     // wsum reused by block_scan below

    int i = blockIdx.x * 256 + t;
    int v = (i < NN) ? g_deg[i] : 0;
    int incl = block_scan_256(v, wsum);
    if (i < NN) g_off[i + 1] = incl + pre;
    if (i == 0) g_off[0] = 0;
}

// ---------------- kernel: scatter edges into CSR ----------------
__global__ void k_scatter(const int* __restrict__ ei, const int* __restrict__ et) {
    int e = blockIdx.x * blockDim.x + threadIdx.x;
    if (e < EE) {
        int dst = ei[EE + e];
        int pos = g_off[dst] + atomicAdd(&g_cur[dst], 1);
        g_edg[pos] = ei[e] | (et[e] << 17);
    }
}

// ---------------- aggregation helpers ----------------
__device__ __forceinline__ void agg_one(
    float4 xi0, float4 xi1, float4 xi2,
    float4 xj0, float4 xj1, float4 xj2,
    int et, int lane,
    const float* __restrict__ init_rel, const float* __restrict__ loop_rel,
    const float* __restrict__ rel_weight,
    float4& acc0, float4& acc1, float4& acc2,
    float& den0, float& den1, float& den2)
{
    const float4* w4 = (const float4*)(rel_weight + (size_t)et * (KK * DD));
    const float4* r4 = (const float4*)((et < LOOP_ET) ? (init_rel + (size_t)et * DD)
                                                      : loop_rel);
    float4 r  = __ldg(r4 + lane);
    float4 w0 = __ldg(w4 + lane);
    float4 w1 = __ldg(w4 + 32 + lane);
    float4 w2 = __ldg(w4 + 64 + lane);

    float4 jw0 = f4mul(xj0, w0);
    float4 jw1 = f4mul(xj1, w1);
    float4 jw2 = f4mul(xj2, w2);

    float p0 = dot4m(f4mul(xi0, w0), jw0);
    float p1 = dot4m(f4mul(xi1, w1), jw1);
    float p2 = dot4m(f4mul(xi2, w2), jw2);
#pragma unroll
    for (int s = 16; s; s >>= 1) {
        p0 += __shfl_xor_sync(0xffffffffu, p0, s);
        p1 += __shfl_xor_sync(0xffffffffu, p1, s);
        p2 += __shfl_xor_sync(0xffffffffu, p2, s);
    }
    float a0 = p0 > 0.f ? p0 : NEG * p0;
    float a1 = p1 > 0.f ? p1 : NEG * p1;
    float a2 = p2 > 0.f ? p2 : NEG * p2;
    float e0 = __expf(a0), e1 = __expf(a1), e2 = __expf(a2);
    den0 += e0; den1 += e1; den2 += e2;

    float4 rp = make_float4(r.x + 1.f, r.y + 1.f, r.z + 1.f, r.w + 1.f);
    f4fma(acc0, f4mul(jw0, rp), e0);
    f4fma(acc1, f4mul(jw1, rp), e1);
    f4fma(acc2, f4mul(jw2, rp), e2);
}

// ---------------- kernel: per-node message + attention + aggregate ----------------
// one warp per destination node; prefetch next edge's x_j gather (MLP=2)
__global__ __launch_bounds__(256) void k_agg(const float* __restrict__ init_rel,
                                             const float* __restrict__ loop_rel,
                                             const float* __restrict__ rel_weight) {
    int warp = (blockIdx.x * 256 + threadIdx.x) >> 5;
    int lane = threadIdx.x & 31;
    if (warp >= NN) return;
    int node = warp;

    const float4* xrow = (const float4*)(g_x + (size_t)node * KD);
    float4 xi0 = __ldcg(xrow + lane);
    float4 xi1 = __ldcg(xrow + 32 + lane);
    float4 xi2 = __ldcg(xrow + 64 + lane);

    float4 acc0 = make_float4(0, 0, 0, 0);
    float4 acc1 = make_float4(0, 0, 0, 0);
    float4 acc2 = make_float4(0, 0, 0, 0);
    float den0 = 0.f, den1 = 0.f, den2 = 0.f;

    // self-loop first (no gather needed)
    agg_one(xi0, xi1, xi2, xi0, xi1, xi2, LOOP_ET, lane,
            init_rel, loop_rel, rel_weight, acc0, acc1, acc2, den0, den1, den2);

    int beg = g_off[node], end = g_off[node + 1];
    if (beg < end) {
        int p = g_edg[beg];
        int net = p >> 17;
        const float4* xs = (const float4*)(g_x + (size_t)(p & 0x1FFFF) * KD);
        float4 nx0 = __ldcg(xs + lane);
        float4 nx1 = __ldcg(xs + 32 + lane);
        float4 nx2 = __ldcg(xs + 64 + lane);

        for (int e = beg; e < end; e++) {
            float4 x0 = nx0, x1 = nx1, x2 = nx2;
            int et = net;
            if (e + 1 < end) {
                int p2 = g_edg[e + 1];
                net = p2 >> 17;
                const float4* xs2 = (const float4*)(g_x + (size_t)(p2 & 0x1FFFF) * KD);
                nx0 = __ldcg(xs2 + lane);
                nx1 = __ldcg(xs2 + 32 + lane);
                nx2 = __ldcg(xs2 + 64 + lane);
            }
            agg_one(xi0, xi1, xi2, x0, x1, x2, et, lane,
                    init_rel, loop_rel, rel_weight, acc0, acc1, acc2, den0, den1, den2);
        }
    }

    float i0 = 1.f / (den0 + 1e-16f);
    float i1 = 1.f / (den1 + 1e-16f);
    float i2 = 1.f / (den2 + 1e-16f);
    float4* orow = (float4*)(g_out + (size_t)node * KD);
    orow[lane]      = make_float4(acc0.x * i0, acc0.y * i0, acc0.z * i0, acc0.w * i0);
    orow[32 + lane] = make_float4(acc1.x * i1, acc1.y * i1, acc1.z * i1, acc1.w * i1);
    orow[64 + lane] = make_float4(acc2.x * i2, acc2.y * i2, acc2.z * i2, acc2.w * i2);
}

// ---------------- kernel: BN column stats ----------------
__global__ void k_bnstats() {
    int col = threadIdx.x;   // blockDim = 384
    float s = 0.f, s2 = 0.f;
    for (int row = blockIdx.x; row < NN; row += gridDim.x) {
        float v = g_out[(size_t)row * KD + col];
        s += v; s2 += v * v;
    }
    atomicAdd(&g_sum[col], s);
    atomicAdd(&g_sumsq[col], s2);
}

// ---------------- kernel: finalize BN coefficients ----------------
__global__ void k_bnfinal(const float* __restrict__ gamma, const float* __restrict__ beta) {
    int c = threadIdx.x;
    if (c < KD) {
        float mu = g_sum[c] / (float)NN;
        float var = g_sumsq[c] / (float)NN - mu * mu;
        float a = gamma[c] * rsqrtf(var + BN_EPS);
        g_a[c] = a;
        g_b[c] = beta[c] - mu * a;
    }
}

// ---------------- kernel: normalize + tanh -> d_out ----------------
__global__ void k_apply(float* __restrict__ out) {
    int i = blockIdx.x * blockDim.x + threadIdx.x;   // float4 index
    if (i < NN * (KD / 4)) {
        int c4 = (i % (KD / 4)) * 4;
        float4 v = *(const float4*)&g_out[(size_t)i * 4];
        float4 y;
        y.x = fast_tanh(v.x * g_a[c4 + 0] + g_b[c4 + 0]);
        y.y = fast_tanh(v.y * g_a[c4 + 1] + g_b[c4 + 1]);
        y.z = fast_tanh(v.z * g_a[c4 + 2] + g_b[c4 + 2]);
        y.w = fast_tanh(v.w * g_a[c4 + 3] + g_b[c4 + 3]);
        ((float4*)out)[i] = y;
    }
}

// ---------------- launch ----------------
extern "C" void kernel_launch(void* const* d_in, const int* in_sizes, int n_in,
                              void* d_out, int out_size) {
    const float* init_embed = (const float*)d_in[0];
    const float* init_rel   = (const float*)d_in[1];
    const float* pca_w      = (const float*)d_in[2];
    const float* pca_b      = (const float*)d_in[3];
    const float* loop_rel   = (const float*)d_in[4];
    const float* rel_weight = (const float*)d_in[5];
    const float* bn_gamma   = (const float*)d_in[6];
    const float* bn_beta    = (const float*)d_in[7];
    const int*   edge_index = (const int*)d_in[8];
    const int*   edge_type  = (const int*)d_in[9];
    float* out = (float*)d_out;

    k_zero<<<(NN + 255) / 256, 256>>>();                       // idx 0
    k_hist<<<(EE + 255) / 256, 256>>>(edge_index);             // idx 1
    k_scanA<<<NBLK, 256>>>();                                  // idx 2

    dim3 gg((NN + 127) / 128, KD / 128);
    k_gemm<<<gg, 256>>>(init_embed, pca_w, pca_b);             // idx 3 <- ncu capture

    k_scanC<<<NBLK, 256>>>();                                  // idx 4
    k_scatter<<<(EE + 255) / 256, 256>>>(edge_index, edge_type); // idx 5

    k_agg<<<(NN * 32 + 255) / 256, 256>>>(init_rel, loop_rel, rel_weight);

    k_bnstats<<<512, 384>>>();
    k_bnfinal<<<1, 384>>>(bn_gamma, bn_beta);
    k_apply<<<(NN * (KD / 4) + 255) / 256, 256>>>(out);
}